// round 15
// baseline (speedup 1.0000x reference)
#include <cuda_runtime.h>
#include <cstdint>

typedef unsigned int u32;
typedef unsigned short u16;

#define D       64
#define K       1024
#define HW      4096
#define BLOCK   128
#define CHUNK   32
#define GROUP   128
#define NGROUPS (K / GROUP)
#define CAPL    8            // u32 slots per q-lane (32 per point)
#define MAXBLK  4096

// dynamic smem layout (bytes)
#define OFF_Z    0          // fp32 z [64][128]                 32768
#define OFF_CN   32768      // fp32 cn[1024]                     4096
#define OFF_CNH  36864      // f16x2 cn pairs [512]              2048
#define OFF_STG  38912      // f16 group [128 codes x 128B, SW]  16384 (1024-aligned)
#define OFF_CAND 55296      // u32 [128][32] (key|idx)          16384
#define OFF_RED  71680      // fp32 [64]                          256
#define SMEM_SZ  71936

__device__ float g_cnorm[K];
__device__ u32   g_cnh[K / 2];
__device__ u32   g_cbpk[K * 32];
__device__ float g_partials[MAXBLK];

__device__ __forceinline__ u32 hf2(float lo, float hi) {
    u32 r;
    asm("cvt.rn.f16x2.f32 %0, %1, %2;" : "=r"(r) : "f"(hi), "f"(lo));
    return r;
}
__device__ __forceinline__ float h2f(u32 hbits) {
    float f;
    asm("{.reg .b16 t; mov.b16 t, %1; cvt.f32.f16 %0, t;}"
        : "=f"(f) : "h"((u16)hbits));
    return f;
}
__device__ __forceinline__ u32 smem_u32(const void* p) {
    u32 a;
    asm("{ .reg .u64 t; cvta.to.shared.u64 t, %1; cvt.u32.u64 %0, t; }"
        : "=r"(a) : "l"(p));
    return a;
}
__device__ __forceinline__ void mma16816h(u32 c[2], const u32 a0, const u32 a1,
                                          const u32 a2, const u32 a3,
                                          const u32 b0, const u32 b1) {
    asm volatile(
        "mma.sync.aligned.m16n8k16.row.col.f16.f16.f16.f16 "
        "{%0,%1}, {%2,%3,%4,%5}, {%6,%7}, {%0,%1};"
        : "+r"(c[0]), "+r"(c[1])
        : "r"(a0), "r"(a1), "r"(a2), "r"(a3), "r"(b0), "r"(b1));
}
__device__ __forceinline__ void ldmx4(u32& r0, u32& r1, u32& r2, u32& r3,
                                      u32 addr) {
    asm volatile(
        "ldmatrix.sync.aligned.m8n8.x4.shared.b16 {%0,%1,%2,%3}, [%4];"
        : "=r"(r0), "=r"(r1), "=r"(r2), "=r"(r3) : "r"(addr));
}
__device__ __forceinline__ u32 hfma2_(u32 a, u32 b, u32 c) {
    u32 d;
    asm("fma.rn.f16x2 %0, %1, %2, %3;" : "=r"(d) : "r"(a), "r"(b), "r"(c));
    return d;
}
__device__ __forceinline__ u32 hmin2_(u32 a, u32 b) {
    u32 d;
    asm("min.f16x2 %0, %1, %2;" : "=r"(d) : "r"(a), "r"(b));
    return d;
}
__device__ __forceinline__ u32 hadd2_(u32 a, u32 b) {
    u32 d;
    asm("add.rn.f16x2 %0, %1, %2;" : "=r"(d) : "r"(a), "r"(b));
    return d;
}
__device__ __forceinline__ u32 hswap_(u32 a) {
    u32 d;
    asm("prmt.b32 %0, %1, %1, 0x1032;" : "=r"(d) : "r"(a));
    return d;
}
__device__ __forceinline__ u32 hle2m_(u32 a, u32 b) {
    u32 d;
    asm("set.le.u32.f16x2 %0, %1, %2;" : "=r"(d) : "r"(a), "r"(b));
    return d;
}
// order-preserving f16 bits -> u16 key (handles sign)
__device__ __forceinline__ u32 fflip(u32 s) {
    u32 sgn = (s >> 15) & 1u;
    return (s ^ (0x8000u | (sgn * 0x7FFFu))) & 0xFFFFu;
}
__device__ __forceinline__ u32 funflip(u32 f) {
    return (f & 0x8000u) ? (f ^ 0x8000u) : (~f & 0xFFFFu);
}

// ||c||^2 (bitwise-sequential) + f16 pack + cn f16x2 table, fused
__global__ void __launch_bounds__(64) cnorm_pack_kernel(const float* __restrict__ cb) {
    __shared__ float sCb[64 * 65];
    __shared__ float sCnA[64];
    const int tid = threadIdx.x;
    const float* src = cb + (size_t)blockIdx.x * 64 * D;
#pragma unroll
    for (int j = 0; j < 64; j++) {
        int idx = tid + j * 64;
        sCb[(idx >> 6) * 65 + (idx & 63)] = src[idx];
    }
    __syncthreads();
    const float* row = sCb + tid * 65;
    float s = 0.f;
#pragma unroll
    for (int d = 0; d < D; d++)
        s = __fadd_rn(s, __fmul_rn(row[d], row[d]));
    const int code = blockIdx.x * 64 + tid;
    g_cnorm[code] = s;
    sCnA[tid] = s;
#pragma unroll
    for (int q = 0; q < 32; q++)
        g_cbpk[code * 32 + q] = hf2(row[2 * q], row[2 * q + 1]);
    __syncthreads();
    if ((tid & 1) == 0)
        g_cnh[code >> 1] = hf2(sCnA[tid], sCnA[tid + 1]);
}

__global__ void dummy1_kernel() {}
__global__ void dummy2_kernel() {}

__global__ void __launch_bounds__(BLOCK, 3)
vq_kernel(const float* __restrict__ z,
          const float* __restrict__ cb,
          float* __restrict__ out,
          long long idxOff) {
    extern __shared__ char smem[];
    float* sZ = (float*)(smem + OFF_Z);
    float* sCn = (float*)(smem + OFF_CN);
    u32* sCnH = (u32*)(smem + OFF_CNH);
    u32* sCand = (u32*)(smem + OFF_CAND);
    float* sRed = (float*)(smem + OFF_RED);
    const u32 sbStg = smem_u32(smem) + OFF_STG;

    const int tid = threadIdx.x;
    const int w = tid >> 5;
    const int lane = tid & 31;
    const int g = lane >> 2;
    const int q = lane & 3;
    const int n = blockIdx.x * BLOCK + tid;
    const int b = n >> 12;
    const int hw = n & (HW - 1);

    // stage z (exact), znorm (bitwise sequential)
    const float* zbase = z + (size_t)b * D * HW + hw;
    float zn = 0.f;
#pragma unroll
    for (int d = 0; d < D; d++) {
        float v = zbase[(size_t)d * HW];
        sZ[d * BLOCK + tid] = v;
        zn = __fadd_rn(zn, __fmul_rn(v, v));
    }
#pragma unroll
    for (int j = 0; j < K / BLOCK; j++)
        sCn[tid + j * BLOCK] = g_cnorm[tid + j * BLOCK];
    ((uint4*)sCnH)[tid] = ((const uint4*)g_cnh)[tid];
#pragma unroll
    for (int j = 0; j < 32; j++)
        sCand[tid + j * BLOCK] = 0xFFFFFFFFu;
    __syncthreads();

    // A fragments (fp16)
    u32 aR[4][4][2];
#pragma unroll
    for (int i = 0; i < 4; i++) {
        const int p = 32 * w + 8 * i + g;
#pragma unroll
        for (int kt = 0; kt < 4; kt++)
#pragma unroll
            for (int h = 0; h < 2; h++) {
                const int k0 = 16 * kt + 8 * h + 2 * q;
                aR[i][kt][h] = hf2(sZ[k0 * BLOCK + p], sZ[(k0 + 1) * BLOCK + p]);
            }
    }

    // block max of cn and zn (for certified delta)
    float mx = 0.f, zm = zn;
#pragma unroll
    for (int j = 0; j < K / BLOCK; j++) mx = fmaxf(mx, sCn[tid + j * BLOCK]);
#pragma unroll
    for (int o = 16; o > 0; o >>= 1) {
        mx = fmaxf(mx, __shfl_xor_sync(0xffffffffu, mx, o));
        zm = fmaxf(zm, __shfl_xor_sync(0xffffffffu, zm, o));
    }
    if (lane == 0) { sRed[w] = mx; sRed[8 + w] = zm; }
    __syncthreads();
    mx = fmaxf(fmaxf(sRed[0], sRed[1]), fmaxf(sRed[2], sRed[3]));
    zm = fmaxf(fmaxf(sRed[8], sRed[9]), fmaxf(sRed[10], sRed[11]));

    const float delta = 0.030f * sqrtf(zm * mx) + 1e-6f * (zm + mx + 1.0f);
    const u32 dl2 = hf2(delta * 1.05f, delta * 1.05f);
    const u32 INF2 = 0x7C007C00u;
    const u32 M2H2 = 0xC000C000u;
    u32 rm2[4] = {INF2, INF2, INF2, INF2};
    int cnt4[4] = {0, 0, 0, 0};

    const int mSel = lane >> 3;
    const int ntOff = mSel >> 1;
    const int hSel = mSel & 1;
    const int rowIn = lane & 7;

#pragma unroll 1
    for (int grp = 0; grp < NGROUPS; grp++) {
        __syncthreads();
        const uint4* gsrc = (const uint4*)(g_cbpk + (size_t)grp * GROUP * 32);
#pragma unroll
        for (int i = 0; i < 8; i++) {
            int idx = tid + 128 * i;
            u32 off = (u32)idx << 4;
            u32 sw = off ^ ((off >> 3) & 0x70);
            *(uint4*)(smem + OFF_STG + sw) = gsrc[idx];
        }
        __syncthreads();

#pragma unroll 1
        for (int c = 0; c < GROUP / CHUNK; c++) {
            const int cbase = grp * GROUP + c * CHUNK;
            const int lbase = c * CHUNK;

            u32 cfr[2][4][2];
#pragma unroll
            for (int mt = 0; mt < 2; mt++)
#pragma unroll
                for (int nt = 0; nt < 4; nt++) {
                    cfr[mt][nt][0] = 0u;
                    cfr[mt][nt][1] = 0u;
                }
#pragma unroll
            for (int kt = 0; kt < 4; kt++) {
                u32 bb[4][2];
#pragma unroll
                for (int np = 0; np < 2; np++) {
                    const int code = lbase + 8 * (2 * np + ntOff) + rowIn;
                    u32 off = (u32)(code * 128 + kt * 32 + hSel * 16);
                    u32 sw = off ^ ((off >> 3) & 0x70);
                    ldmx4(bb[2 * np][0], bb[2 * np][1],
                          bb[2 * np + 1][0], bb[2 * np + 1][1], sbStg + sw);
                }
#pragma unroll
                for (int mt = 0; mt < 2; mt++)
#pragma unroll
                    for (int nt = 0; nt < 4; nt++)
                        mma16816h(cfr[mt][nt],
                                  aR[2 * mt][kt][0], aR[2 * mt + 1][kt][0],
                                  aR[2 * mt][kt][1], aR[2 * mt + 1][kt][1],
                                  bb[nt][0], bb[nt][1]);
            }

            // fp16x2 screen fast path; inserts carry the f16 score
            u32 cnH[4];
#pragma unroll
            for (int nt = 0; nt < 4; nt++)
                cnH[nt] = sCnH[(cbase >> 1) + 4 * nt + q];
#pragma unroll
            for (int i = 0; i < 4; i++) {
                u32 s0 = hfma2_(cfr[i >> 1][0][i & 1], M2H2, cnH[0]);
                u32 s1 = hfma2_(cfr[i >> 1][1][i & 1], M2H2, cnH[1]);
                u32 s2 = hfma2_(cfr[i >> 1][2][i & 1], M2H2, cnH[2]);
                u32 s3 = hfma2_(cfr[i >> 1][3][i & 1], M2H2, cnH[3]);
                u32 m = hmin2_(hmin2_(s0, s1), hmin2_(s2, s3));
                m = hmin2_(m, hswap_(m));
                rm2[i] = hmin2_(rm2[i], m);
                u32 thr = hadd2_(rm2[i], dl2);
                if (hle2m_(m, thr)) {
                    u32 k0 = hle2m_(s0, thr), k1 = hle2m_(s1, thr);
                    u32 k2 = hle2m_(s2, thr), k3 = hle2m_(s3, thr);
                    const int pidx = 32 * w + 8 * i + g;
                    u32* lst = sCand + pidx * 32 + q * CAPL;
                    u32 mk[4] = {k0, k1, k2, k3};
                    u32 sv[4] = {s0, s1, s2, s3};
#pragma unroll
                    for (int nt = 0; nt < 4; nt++) {
                        if (mk[nt] & 0xFFFFu) {
                            if (cnt4[i] < CAPL)
                                lst[cnt4[i]] = (fflip(sv[nt] & 0xFFFFu) << 16) |
                                               (u32)(cbase + 8 * nt + 2 * q);
                            cnt4[i]++;
                        }
                        if (mk[nt] >> 16) {
                            if (cnt4[i] < CAPL)
                                lst[cnt4[i]] = (fflip(sv[nt] >> 16) << 16) |
                                               (u32)(cbase + 8 * nt + 2 * q + 1);
                            cnt4[i]++;
                        }
                    }
                }
            }
#pragma unroll
            for (int i = 0; i < 4; i++) {
                rm2[i] = hmin2_(rm2[i], __shfl_xor_sync(0xffffffffu, rm2[i], 1));
                rm2[i] = hmin2_(rm2[i], __shfl_xor_sync(0xffffffffu, rm2[i], 2));
            }
        }
    }

    // overflow markers (key high half 0xFFFE)
#pragma unroll
    for (int i = 0; i < 4; i++)
        if (cnt4[i] > CAPL) {
            const int pidx = 32 * w + 8 * i + g;
            sCand[pidx * 32 + q * CAPL + CAPL - 1] = 0xFFFE0000u;
        }
    __syncwarp();

    // refine pass 1: zero-load score min over this point's list
    u32 minkey = 0xFFFFFFFFu;
    bool ovf = false;
#pragma unroll
    for (int s = 0; s < 32; s++) {
        u32 kk = sCand[tid * 32 + s];
        if ((kk >> 16) == 0xFFFEu) { ovf = true; continue; }
        minkey = min(minkey, kk);
    }
    const float minsc = h2f(funflip(minkey >> 16));
    const float thrsc = minsc + delta * 1.05f;

    // refine pass 2: exact eval only certified-near candidates
    float best = 3.4e38f;
    int bestk = 0x7FFFFFFF;
    if (!ovf && minkey != 0xFFFFFFFFu) {
#pragma unroll 1
        for (int s = 0; s < 32; s++) {
            u32 kk = sCand[tid * 32 + s];
            if (kk >= 0xFFFE0000u) continue;
            if (h2f(funflip(kk >> 16)) > thrsc) continue;
            const int code = (int)(kk & 0xFFFFu);
            const float4* crow = (const float4*)(cb + (size_t)code * D);
            float dot = 0.f;
#pragma unroll
            for (int qd = 0; qd < 16; qd++) {
                float4 c4 = __ldg(&crow[qd]);
                dot = __fmaf_rn(sZ[(4 * qd + 0) * BLOCK + tid], c4.x, dot);
                dot = __fmaf_rn(sZ[(4 * qd + 1) * BLOCK + tid], c4.y, dot);
                dot = __fmaf_rn(sZ[(4 * qd + 2) * BLOCK + tid], c4.z, dot);
                dot = __fmaf_rn(sZ[(4 * qd + 3) * BLOCK + tid], c4.w, dot);
            }
            float dist = __fsub_rn(__fadd_rn(zn, sCn[code]), __fmul_rn(2.0f, dot));
            if (dist < best || (dist == best && code < bestk)) {
                best = dist; bestk = code;
            }
        }
    } else {
        // exhaustive exact fallback (never wrong)
        best = 3.4e38f; bestk = 0;
#pragma unroll 1
        for (int code = 0; code < K; code++) {
            const float4* crow = (const float4*)(cb + (size_t)code * D);
            float dot = 0.f;
#pragma unroll
            for (int qd = 0; qd < 16; qd++) {
                float4 c4 = __ldg(&crow[qd]);
                dot = __fmaf_rn(sZ[(4 * qd + 0) * BLOCK + tid], c4.x, dot);
                dot = __fmaf_rn(sZ[(4 * qd + 1) * BLOCK + tid], c4.y, dot);
                dot = __fmaf_rn(sZ[(4 * qd + 2) * BLOCK + tid], c4.z, dot);
                dot = __fmaf_rn(sZ[(4 * qd + 3) * BLOCK + tid], c4.w, dot);
            }
            float dist = __fsub_rn(__fadd_rn(zn, sCn[code]), __fmul_rn(2.0f, dot));
            if (dist < best) { best = dist; bestk = code; }
        }
    }

    // epilogue (bitwise recipes from R3)
    const float4* qrow = (const float4*)(cb + (size_t)bestk * D);
    float* outz = out + (size_t)b * D * HW + hw;
    float sumsq = 0.f;
#pragma unroll
    for (int i = 0; i < 16; i++) {
        float4 qv = __ldg(&qrow[i]);
        float qq[4] = {qv.x, qv.y, qv.z, qv.w};
#pragma unroll
        for (int j = 0; j < 4; j++) {
            float zv = sZ[(4 * i + j) * BLOCK + tid];
            float dd = __fsub_rn(qq[j], zv);
            float ov = __fadd_rn(zv, dd);
            sumsq += __fmul_rn(dd, dd);
            outz[(size_t)(4 * i + j) * HW] = ov;
        }
    }
    if (idxOff >= 0) out[idxOff + n] = (float)bestk;

#pragma unroll
    for (int o = 16; o > 0; o >>= 1)
        sumsq += __shfl_down_sync(0xffffffffu, sumsq, o);
    __syncthreads();
    if (lane == 0) sRed[w] = sumsq;
    __syncthreads();
    if (tid == 0) {
        float tot = 0.f;
#pragma unroll
        for (int ww = 0; ww < BLOCK / 32; ww++) tot += sRed[ww];
        g_partials[blockIdx.x] = tot;
    }
}

__global__ void loss_kernel(float* __restrict__ out, int nBlocks,
                            long long lossOff, float invN) {
    __shared__ float s[512];
    int tid = threadIdx.x;
    float v = 0.f;
    for (int i = tid; i < nBlocks; i += 512) v += g_partials[i];
    s[tid] = v;
    __syncthreads();
    for (int st = 256; st > 0; st >>= 1) {
        if (tid < st) s[tid] += s[tid + st];
        __syncthreads();
    }
    if (tid == 0 && lossOff >= 0) {
        float m = __fmul_rn(s[0], invN);
        out[lossOff] = __fadd_rn(m, __fmul_rn(0.25f, m));
    }
}

extern "C" void kernel_launch(void* const* d_in, const int* in_sizes, int n_in,
                              void* d_out, int out_size) {
    const float* z = (const float*)d_in[0];
    const float* cb = (const float*)d_in[1];
    float* out = (float*)d_out;

    const int zElems = in_sizes[0];        // 8388608
    const int nPoints = zElems / D;        // 131072
    const int nBlocks = nPoints / BLOCK;   // 1024

    long long lossOff = ((long long)out_size > (long long)zElems) ? (long long)zElems : -1;
    long long idxOff  = ((long long)out_size >= (long long)zElems + 1 + nPoints)
                            ? (long long)zElems + 1 : -1;

    cudaFuncSetAttribute(vq_kernel, cudaFuncAttributeMaxDynamicSharedMemorySize,
                         SMEM_SZ);

    cnorm_pack_kernel<<<K / 64, 64>>>(cb);
    dummy1_kernel<<<1, 32>>>();
    dummy2_kernel<<<1, 32>>>();
    vq_kernel<<<nBlocks, BLOCK, SMEM_SZ>>>(z, cb, out, idxOff);
    loss_kernel<<<1, 512>>>(out, nBlocks, lossOff, 1.0f / (float)zElems);
}

// round 16
// speedup vs baseline: 4.9211x; 4.9211x over previous
#include <cuda_runtime.h>
#include <cstdint>

typedef unsigned int u32;
typedef unsigned short u16;

#define D       64
#define K       1024
#define HW      4096
#define BLOCK   128
#define CHUNK   32
#define GROUP   64
#define NGROUPS (K / GROUP)
#define CAPL    16           // u32 slots per q-lane (64 per point)
#define MAXBLK  4096

// dynamic smem layout (bytes)
#define OFF_Z    0          // fp32 z [64][128]                 32768
#define OFF_CNH  32768      // f16x2 cn pairs [512]              2048
#define OFF_STG  34816      // f16 group [64 codes x 128B, SW]   8192 (1024-aligned)
#define OFF_CAND 43008      // u32 [128][64] (key|idx)          32768
#define OFF_RED  75776      // fp32 [64]                          256
#define SMEM_SZ  76032

__device__ float g_cnorm[K];
__device__ u32   g_cnh[K / 2];
__device__ u32   g_cbpk[K * 32];
__device__ float g_partials[MAXBLK];

__device__ __forceinline__ u32 hf2(float lo, float hi) {
    u32 r;
    asm("cvt.rn.f16x2.f32 %0, %1, %2;" : "=r"(r) : "f"(hi), "f"(lo));
    return r;
}
__device__ __forceinline__ float h2f(u32 hbits) {
    float f;
    asm("{.reg .b16 t; mov.b16 t, %1; cvt.f32.f16 %0, t;}"
        : "=f"(f) : "h"((u16)hbits));
    return f;
}
__device__ __forceinline__ u32 smem_u32(const void* p) {
    u32 a;
    asm("{ .reg .u64 t; cvta.to.shared.u64 t, %1; cvt.u32.u64 %0, t; }"
        : "=r"(a) : "l"(p));
    return a;
}
__device__ __forceinline__ void mma16816h(u32 c[2], const u32 a0, const u32 a1,
                                          const u32 a2, const u32 a3,
                                          const u32 b0, const u32 b1) {
    asm volatile(
        "mma.sync.aligned.m16n8k16.row.col.f16.f16.f16.f16 "
        "{%0,%1}, {%2,%3,%4,%5}, {%6,%7}, {%0,%1};"
        : "+r"(c[0]), "+r"(c[1])
        : "r"(a0), "r"(a1), "r"(a2), "r"(a3), "r"(b0), "r"(b1));
}
__device__ __forceinline__ void ldmx4(u32& r0, u32& r1, u32& r2, u32& r3,
                                      u32 addr) {
    asm volatile(
        "ldmatrix.sync.aligned.m8n8.x4.shared.b16 {%0,%1,%2,%3}, [%4];"
        : "=r"(r0), "=r"(r1), "=r"(r2), "=r"(r3) : "r"(addr));
}
__device__ __forceinline__ u32 hfma2_(u32 a, u32 b, u32 c) {
    u32 d;
    asm("fma.rn.f16x2 %0, %1, %2, %3;" : "=r"(d) : "r"(a), "r"(b), "r"(c));
    return d;
}
__device__ __forceinline__ u32 hmin2_(u32 a, u32 b) {
    u32 d;
    asm("min.f16x2 %0, %1, %2;" : "=r"(d) : "r"(a), "r"(b));
    return d;
}
__device__ __forceinline__ u32 hadd2_(u32 a, u32 b) {
    u32 d;
    asm("add.rn.f16x2 %0, %1, %2;" : "=r"(d) : "r"(a), "r"(b));
    return d;
}
__device__ __forceinline__ u32 hswap_(u32 a) {
    u32 d;
    asm("prmt.b32 %0, %1, %1, 0x1032;" : "=r"(d) : "r"(a));
    return d;
}
__device__ __forceinline__ u32 hle2m_(u32 a, u32 b) {
    u32 d;
    asm("set.le.u32.f16x2 %0, %1, %2;" : "=r"(d) : "r"(a), "r"(b));
    return d;
}
// order-preserving f16 bits -> u16 key (handles sign)
__device__ __forceinline__ u32 fflip(u32 s) {
    u32 sgn = (s >> 15) & 1u;
    return (s ^ (0x8000u | (sgn * 0x7FFFu))) & 0xFFFFu;
}
__device__ __forceinline__ u32 funflip(u32 f) {
    return (f & 0x8000u) ? (f ^ 0x8000u) : (~f & 0xFFFFu);
}

// ||c||^2 (bitwise-sequential) + f16 pack + cn f16x2 table, fused
__global__ void __launch_bounds__(64) cnorm_pack_kernel(const float* __restrict__ cb) {
    __shared__ float sCb[64 * 65];
    __shared__ float sCnA[64];
    const int tid = threadIdx.x;
    const float* src = cb + (size_t)blockIdx.x * 64 * D;
#pragma unroll
    for (int j = 0; j < 64; j++) {
        int idx = tid + j * 64;
        sCb[(idx >> 6) * 65 + (idx & 63)] = src[idx];
    }
    __syncthreads();
    const float* row = sCb + tid * 65;
    float s = 0.f;
#pragma unroll
    for (int d = 0; d < D; d++)
        s = __fadd_rn(s, __fmul_rn(row[d], row[d]));
    const int code = blockIdx.x * 64 + tid;
    g_cnorm[code] = s;
    sCnA[tid] = s;
#pragma unroll
    for (int q = 0; q < 32; q++)
        g_cbpk[code * 32 + q] = hf2(row[2 * q], row[2 * q + 1]);
    __syncthreads();
    if ((tid & 1) == 0)
        g_cnh[code >> 1] = hf2(sCnA[tid], sCnA[tid + 1]);
}

__global__ void dummy1_kernel() {}
__global__ void dummy2_kernel() {}

__global__ void __launch_bounds__(BLOCK, 3)
vq_kernel(const float* __restrict__ z,
          const float* __restrict__ cb,
          float* __restrict__ out,
          long long idxOff) {
    extern __shared__ char smem[];
    float* sZ = (float*)(smem + OFF_Z);
    u32* sCnH = (u32*)(smem + OFF_CNH);
    u32* sCand = (u32*)(smem + OFF_CAND);
    float* sRed = (float*)(smem + OFF_RED);
    const u32 sbStg = smem_u32(smem) + OFF_STG;

    const int tid = threadIdx.x;
    const int w = tid >> 5;
    const int lane = tid & 31;
    const int g = lane >> 2;
    const int q = lane & 3;
    const int n = blockIdx.x * BLOCK + tid;
    const int b = n >> 12;
    const int hw = n & (HW - 1);

    // stage z (exact), znorm (bitwise sequential)
    const float* zbase = z + (size_t)b * D * HW + hw;
    float zn = 0.f;
#pragma unroll
    for (int d = 0; d < D; d++) {
        float v = zbase[(size_t)d * HW];
        sZ[d * BLOCK + tid] = v;
        zn = __fadd_rn(zn, __fmul_rn(v, v));
    }
    ((uint4*)sCnH)[tid] = ((const uint4*)g_cnh)[tid];
#pragma unroll
    for (int j = 0; j < 64; j++)
        sCand[tid + j * BLOCK] = 0xFFFFFFFFu;
    __syncthreads();

    // A fragments (fp16)
    u32 aR[4][4][2];
#pragma unroll
    for (int i = 0; i < 4; i++) {
        const int p = 32 * w + 8 * i + g;
#pragma unroll
        for (int kt = 0; kt < 4; kt++)
#pragma unroll
            for (int h = 0; h < 2; h++) {
                const int k0 = 16 * kt + 8 * h + 2 * q;
                aR[i][kt][h] = hf2(sZ[k0 * BLOCK + p], sZ[(k0 + 1) * BLOCK + p]);
            }
    }

    // block max of cn and zn (for certified delta)
    float mx = 0.f, zm = zn;
#pragma unroll
    for (int j = 0; j < K / BLOCK; j++)
        mx = fmaxf(mx, __ldg(&g_cnorm[tid + j * BLOCK]));
#pragma unroll
    for (int o = 16; o > 0; o >>= 1) {
        mx = fmaxf(mx, __shfl_xor_sync(0xffffffffu, mx, o));
        zm = fmaxf(zm, __shfl_xor_sync(0xffffffffu, zm, o));
    }
    if (lane == 0) { sRed[w] = mx; sRed[8 + w] = zm; }
    __syncthreads();
    mx = fmaxf(fmaxf(sRed[0], sRed[1]), fmaxf(sRed[2], sRed[3]));
    zm = fmaxf(fmaxf(sRed[8], sRed[9]), fmaxf(sRed[10], sRed[11]));

    const float delta = 0.030f * sqrtf(zm * mx) + 1e-6f * (zm + mx + 1.0f);
    const u32 dl2 = hf2(delta * 1.05f, delta * 1.05f);
    const u32 INF2 = 0x7C007C00u;
    const u32 M2H2 = 0xC000C000u;
    u32 rm2[4] = {INF2, INF2, INF2, INF2};
    int cnt4[4] = {0, 0, 0, 0};

    const int mSel = lane >> 3;
    const int ntOff = mSel >> 1;
    const int hSel = mSel & 1;
    const int rowIn = lane & 7;

#pragma unroll 1
    for (int grp = 0; grp < NGROUPS; grp++) {
        __syncthreads();
        const uint4* gsrc = (const uint4*)(g_cbpk + (size_t)grp * GROUP * 32);
#pragma unroll
        for (int i = 0; i < 4; i++) {
            int idx = tid + 128 * i;
            u32 off = (u32)idx << 4;
            u32 sw = off ^ ((off >> 3) & 0x70);
            *(uint4*)(smem + OFF_STG + sw) = gsrc[idx];
        }
        __syncthreads();

#pragma unroll 1
        for (int c = 0; c < GROUP / CHUNK; c++) {
            const int cbase = grp * GROUP + c * CHUNK;
            const int lbase = c * CHUNK;

            u32 cfr[2][4][2];
#pragma unroll
            for (int mt = 0; mt < 2; mt++)
#pragma unroll
                for (int nt = 0; nt < 4; nt++) {
                    cfr[mt][nt][0] = 0u;
                    cfr[mt][nt][1] = 0u;
                }
#pragma unroll
            for (int kt = 0; kt < 4; kt++) {
                u32 bb[4][2];
#pragma unroll
                for (int np = 0; np < 2; np++) {
                    const int code = lbase + 8 * (2 * np + ntOff) + rowIn;
                    u32 off = (u32)(code * 128 + kt * 32 + hSel * 16);
                    u32 sw = off ^ ((off >> 3) & 0x70);
                    ldmx4(bb[2 * np][0], bb[2 * np][1],
                          bb[2 * np + 1][0], bb[2 * np + 1][1], sbStg + sw);
                }
#pragma unroll
                for (int mt = 0; mt < 2; mt++)
#pragma unroll
                    for (int nt = 0; nt < 4; nt++)
                        mma16816h(cfr[mt][nt],
                                  aR[2 * mt][kt][0], aR[2 * mt + 1][kt][0],
                                  aR[2 * mt][kt][1], aR[2 * mt + 1][kt][1],
                                  bb[nt][0], bb[nt][1]);
            }

            // fp16x2 screen fast path; inserts carry the f16 score
            u32 cnH[4];
#pragma unroll
            for (int nt = 0; nt < 4; nt++)
                cnH[nt] = sCnH[(cbase >> 1) + 4 * nt + q];
#pragma unroll
            for (int i = 0; i < 4; i++) {
                u32 s0 = hfma2_(cfr[i >> 1][0][i & 1], M2H2, cnH[0]);
                u32 s1 = hfma2_(cfr[i >> 1][1][i & 1], M2H2, cnH[1]);
                u32 s2 = hfma2_(cfr[i >> 1][2][i & 1], M2H2, cnH[2]);
                u32 s3 = hfma2_(cfr[i >> 1][3][i & 1], M2H2, cnH[3]);
                u32 m = hmin2_(hmin2_(s0, s1), hmin2_(s2, s3));
                m = hmin2_(m, hswap_(m));
                rm2[i] = hmin2_(rm2[i], m);
                u32 thr = hadd2_(rm2[i], dl2);
                if (hle2m_(m, thr)) {
                    u32 k0 = hle2m_(s0, thr), k1 = hle2m_(s1, thr);
                    u32 k2 = hle2m_(s2, thr), k3 = hle2m_(s3, thr);
                    const int pidx = 32 * w + 8 * i + g;
                    u32* lst = sCand + pidx * 64 + q * CAPL;
                    u32 mk[4] = {k0, k1, k2, k3};
                    u32 sv[4] = {s0, s1, s2, s3};
#pragma unroll
                    for (int nt = 0; nt < 4; nt++) {
                        if (mk[nt] & 0xFFFFu) {
                            if (cnt4[i] < CAPL)
                                lst[cnt4[i]] = (fflip(sv[nt] & 0xFFFFu) << 16) |
                                               (u32)(cbase + 8 * nt + 2 * q);
                            cnt4[i]++;
                        }
                        if (mk[nt] >> 16) {
                            if (cnt4[i] < CAPL)
                                lst[cnt4[i]] = (fflip(sv[nt] >> 16) << 16) |
                                               (u32)(cbase + 8 * nt + 2 * q + 1);
                            cnt4[i]++;
                        }
                    }
                }
            }
#pragma unroll
            for (int i = 0; i < 4; i++) {
                rm2[i] = hmin2_(rm2[i], __shfl_xor_sync(0xffffffffu, rm2[i], 1));
                rm2[i] = hmin2_(rm2[i], __shfl_xor_sync(0xffffffffu, rm2[i], 2));
            }
        }
    }

    // overflow markers (key high half 0xFFFE)
#pragma unroll
    for (int i = 0; i < 4; i++)
        if (cnt4[i] > CAPL) {
            const int pidx = 32 * w + 8 * i + g;
            sCand[pidx * 64 + q * CAPL + CAPL - 1] = 0xFFFE0000u;
        }
    __syncwarp();

    // refine pass 1: zero-load score min over this point's list
    u32 minkey = 0xFFFFFFFFu;
    bool ovf = false;
#pragma unroll
    for (int s = 0; s < 64; s++) {
        u32 kk = sCand[tid * 64 + s];
        if ((kk >> 16) == 0xFFFEu) { ovf = true; continue; }
        minkey = min(minkey, kk);
    }
    const float minsc = h2f(funflip(minkey >> 16));
    const float thrsc = minsc + delta * 1.05f;

    // refine pass 2: exact eval only certified-near candidates
    float best = 3.4e38f;
    int bestk = 0x7FFFFFFF;
    if (!ovf && minkey != 0xFFFFFFFFu) {
#pragma unroll 1
        for (int s = 0; s < 64; s++) {
            u32 kk = sCand[tid * 64 + s];
            if (kk >= 0xFFFE0000u) continue;
            if (h2f(funflip(kk >> 16)) > thrsc) continue;
            const int code = (int)(kk & 0xFFFFu);
            const float4* crow = (const float4*)(cb + (size_t)code * D);
            float dot = 0.f;
#pragma unroll
            for (int qd = 0; qd < 16; qd++) {
                float4 c4 = __ldg(&crow[qd]);
                dot = __fmaf_rn(sZ[(4 * qd + 0) * BLOCK + tid], c4.x, dot);
                dot = __fmaf_rn(sZ[(4 * qd + 1) * BLOCK + tid], c4.y, dot);
                dot = __fmaf_rn(sZ[(4 * qd + 2) * BLOCK + tid], c4.z, dot);
                dot = __fmaf_rn(sZ[(4 * qd + 3) * BLOCK + tid], c4.w, dot);
            }
            float dist = __fsub_rn(__fadd_rn(zn, __ldg(&g_cnorm[code])),
                                   __fmul_rn(2.0f, dot));
            if (dist < best || (dist == best && code < bestk)) {
                best = dist; bestk = code;
            }
        }
    } else {
        // exhaustive exact fallback (never wrong)
        best = 3.4e38f; bestk = 0;
#pragma unroll 1
        for (int code = 0; code < K; code++) {
            const float4* crow = (const float4*)(cb + (size_t)code * D);
            float dot = 0.f;
#pragma unroll
            for (int qd = 0; qd < 16; qd++) {
                float4 c4 = __ldg(&crow[qd]);
                dot = __fmaf_rn(sZ[(4 * qd + 0) * BLOCK + tid], c4.x, dot);
                dot = __fmaf_rn(sZ[(4 * qd + 1) * BLOCK + tid], c4.y, dot);
                dot = __fmaf_rn(sZ[(4 * qd + 2) * BLOCK + tid], c4.z, dot);
                dot = __fmaf_rn(sZ[(4 * qd + 3) * BLOCK + tid], c4.w, dot);
            }
            float dist = __fsub_rn(__fadd_rn(zn, __ldg(&g_cnorm[code])),
                                   __fmul_rn(2.0f, dot));
            if (dist < best) { best = dist; bestk = code; }
        }
    }

    // epilogue (bitwise recipes from R3)
    const float4* qrow = (const float4*)(cb + (size_t)bestk * D);
    float* outz = out + (size_t)b * D * HW + hw;
    float sumsq = 0.f;
#pragma unroll
    for (int i = 0; i < 16; i++) {
        float4 qv = __ldg(&qrow[i]);
        float qq[4] = {qv.x, qv.y, qv.z, qv.w};
#pragma unroll
        for (int j = 0; j < 4; j++) {
            float zv = sZ[(4 * i + j) * BLOCK + tid];
            float dd = __fsub_rn(qq[j], zv);
            float ov = __fadd_rn(zv, dd);
            sumsq += __fmul_rn(dd, dd);
            outz[(size_t)(4 * i + j) * HW] = ov;
        }
    }
    if (idxOff >= 0) out[idxOff + n] = (float)bestk;

#pragma unroll
    for (int o = 16; o > 0; o >>= 1)
        sumsq += __shfl_down_sync(0xffffffffu, sumsq, o);
    __syncthreads();
    if (lane == 0) sRed[w] = sumsq;
    __syncthreads();
    if (tid == 0) {
        float tot = 0.f;
#pragma unroll
        for (int ww = 0; ww < BLOCK / 32; ww++) tot += sRed[ww];
        g_partials[blockIdx.x] = tot;
    }
}

__global__ void loss_kernel(float* __restrict__ out, int nBlocks,
                            long long lossOff, float invN) {
    __shared__ float s[512];
    int tid = threadIdx.x;
    float v = 0.f;
    for (int i = tid; i < nBlocks; i += 512) v += g_partials[i];
    s[tid] = v;
    __syncthreads();
    for (int st = 256; st > 0; st >>= 1) {
        if (tid < st) s[tid] += s[tid + st];
        __syncthreads();
    }
    if (tid == 0 && lossOff >= 0) {
        float m = __fmul_rn(s[0], invN);
        out[lossOff] = __fadd_rn(m, __fmul_rn(0.25f, m));
    }
}

extern "C" void kernel_launch(void* const* d_in, const int* in_sizes, int n_in,
                              void* d_out, int out_size) {
    const float* z = (const float*)d_in[0];
    const float* cb = (const float*)d_in[1];
    float* out = (float*)d_out;

    const int zElems = in_sizes[0];        // 8388608
    const int nPoints = zElems / D;        // 131072
    const int nBlocks = nPoints / BLOCK;   // 1024

    long long lossOff = ((long long)out_size > (long long)zElems) ? (long long)zElems : -1;
    long long idxOff  = ((long long)out_size >= (long long)zElems + 1 + nPoints)
                            ? (long long)zElems + 1 : -1;

    cudaFuncSetAttribute(vq_kernel, cudaFuncAttributeMaxDynamicSharedMemorySize,
                         SMEM_SZ);

    cnorm_pack_kernel<<<K / 64, 64>>>(cb);
    dummy1_kernel<<<1, 32>>>();
    dummy2_kernel<<<1, 32>>>();
    vq_kernel<<<nBlocks, BLOCK, SMEM_SZ>>>(z, cb, out, idxOff);
    loss_kernel<<<1, 512>>>(out, nBlocks, lossOff, 1.0f / (float)zElems);
}

// round 17
// speedup vs baseline: 5.2076x; 1.0582x over previous
#include <cuda_runtime.h>
#include <cstdint>

typedef unsigned int u32;
typedef unsigned short u16;

#define D       64
#define K       1024
#define HW      4096
#define BLOCK   128
#define CHUNK   32
#define GROUP   64
#define NGROUPS (K / GROUP)
#define CAPL    16           // u32 slots per q-lane (64 per point)
#define MAXBLK  4096

// dynamic smem layout (bytes)
#define OFF_Z    0          // fp32 z [64][128]                 32768
#define OFF_CNH  32768      // f16x2 cn pairs [512]              2048
#define OFF_STG  34816      // f16 group [64 codes x 128B, SW]   8192 (1024-aligned)
#define OFF_CAND 43008      // u32 [64 slots][128 points]       32768
#define OFF_RED  75776      // fp32 [64]                          256
#define SMEM_SZ  76032

__device__ float g_cnorm[K];
__device__ u32   g_cnh[K / 2];
__device__ u32   g_cbpk[K * 32];
__device__ float g_partials[MAXBLK];

__device__ __forceinline__ u32 hf2(float lo, float hi) {
    u32 r;
    asm("cvt.rn.f16x2.f32 %0, %1, %2;" : "=r"(r) : "f"(hi), "f"(lo));
    return r;
}
__device__ __forceinline__ float h2f(u32 hbits) {
    float f;
    asm("{.reg .b16 t; mov.b16 t, %1; cvt.f32.f16 %0, t;}"
        : "=f"(f) : "h"((u16)hbits));
    return f;
}
__device__ __forceinline__ u32 smem_u32(const void* p) {
    u32 a;
    asm("{ .reg .u64 t; cvta.to.shared.u64 t, %1; cvt.u32.u64 %0, t; }"
        : "=r"(a) : "l"(p));
    return a;
}
__device__ __forceinline__ void mma16816h(u32 c[2], const u32 a0, const u32 a1,
                                          const u32 a2, const u32 a3,
                                          const u32 b0, const u32 b1) {
    asm volatile(
        "mma.sync.aligned.m16n8k16.row.col.f16.f16.f16.f16 "
        "{%0,%1}, {%2,%3,%4,%5}, {%6,%7}, {%0,%1};"
        : "+r"(c[0]), "+r"(c[1])
        : "r"(a0), "r"(a1), "r"(a2), "r"(a3), "r"(b0), "r"(b1));
}
__device__ __forceinline__ void ldmx4(u32& r0, u32& r1, u32& r2, u32& r3,
                                      u32 addr) {
    asm volatile(
        "ldmatrix.sync.aligned.m8n8.x4.shared.b16 {%0,%1,%2,%3}, [%4];"
        : "=r"(r0), "=r"(r1), "=r"(r2), "=r"(r3) : "r"(addr));
}
__device__ __forceinline__ u32 hfma2_(u32 a, u32 b, u32 c) {
    u32 d;
    asm("fma.rn.f16x2 %0, %1, %2, %3;" : "=r"(d) : "r"(a), "r"(b), "r"(c));
    return d;
}
__device__ __forceinline__ u32 hmin2_(u32 a, u32 b) {
    u32 d;
    asm("min.f16x2 %0, %1, %2;" : "=r"(d) : "r"(a), "r"(b));
    return d;
}
__device__ __forceinline__ u32 hadd2_(u32 a, u32 b) {
    u32 d;
    asm("add.rn.f16x2 %0, %1, %2;" : "=r"(d) : "r"(a), "r"(b));
    return d;
}
__device__ __forceinline__ u32 hswap_(u32 a) {
    u32 d;
    asm("prmt.b32 %0, %1, %1, 0x1032;" : "=r"(d) : "r"(a));
    return d;
}
__device__ __forceinline__ u32 hle2m_(u32 a, u32 b) {
    u32 d;
    asm("set.le.u32.f16x2 %0, %1, %2;" : "=r"(d) : "r"(a), "r"(b));
    return d;
}
// order-preserving f16 bits -> u16 key (handles sign)
__device__ __forceinline__ u32 fflip(u32 s) {
    u32 sgn = (s >> 15) & 1u;
    return (s ^ (0x8000u | (sgn * 0x7FFFu))) & 0xFFFFu;
}
__device__ __forceinline__ u32 funflip(u32 f) {
    return (f & 0x8000u) ? (f ^ 0x8000u) : (~f & 0xFFFFu);
}

// ||c||^2 (bitwise-sequential) + f16 pack + cn f16x2 table, fused
__global__ void __launch_bounds__(64) cnorm_pack_kernel(const float* __restrict__ cb) {
    __shared__ float sCb[64 * 65];
    __shared__ float sCnA[64];
    const int tid = threadIdx.x;
    const float* src = cb + (size_t)blockIdx.x * 64 * D;
#pragma unroll
    for (int j = 0; j < 64; j++) {
        int idx = tid + j * 64;
        sCb[(idx >> 6) * 65 + (idx & 63)] = src[idx];
    }
    __syncthreads();
    const float* row = sCb + tid * 65;
    float s = 0.f;
#pragma unroll
    for (int d = 0; d < D; d++)
        s = __fadd_rn(s, __fmul_rn(row[d], row[d]));
    const int code = blockIdx.x * 64 + tid;
    g_cnorm[code] = s;
    sCnA[tid] = s;
#pragma unroll
    for (int q = 0; q < 32; q++)
        g_cbpk[code * 32 + q] = hf2(row[2 * q], row[2 * q + 1]);
    __syncthreads();
    if ((tid & 1) == 0)
        g_cnh[code >> 1] = hf2(sCnA[tid], sCnA[tid + 1]);
}

__global__ void dummy1_kernel() {}
__global__ void dummy2_kernel() {}

__global__ void __launch_bounds__(BLOCK, 3)
vq_kernel(const float* __restrict__ z,
          const float* __restrict__ cb,
          float* __restrict__ out,
          long long idxOff) {
    extern __shared__ char smem[];
    float* sZ = (float*)(smem + OFF_Z);
    u32* sCnH = (u32*)(smem + OFF_CNH);
    u32* sCand = (u32*)(smem + OFF_CAND);   // [slot][point]
    float* sRed = (float*)(smem + OFF_RED);
    const u32 sbStg = smem_u32(smem) + OFF_STG;

    const int tid = threadIdx.x;
    const int w = tid >> 5;
    const int lane = tid & 31;
    const int g = lane >> 2;
    const int q = lane & 3;
    const int n = blockIdx.x * BLOCK + tid;
    const int b = n >> 12;
    const int hw = n & (HW - 1);

    // stage z (exact), znorm (bitwise sequential)
    const float* zbase = z + (size_t)b * D * HW + hw;
    float zn = 0.f;
#pragma unroll
    for (int d = 0; d < D; d++) {
        float v = zbase[(size_t)d * HW];
        sZ[d * BLOCK + tid] = v;
        zn = __fadd_rn(zn, __fmul_rn(v, v));
    }
    ((uint4*)sCnH)[tid] = ((const uint4*)g_cnh)[tid];
#pragma unroll
    for (int j = 0; j < 64; j++)
        sCand[j * BLOCK + tid] = 0xFFFFFFFFu;
    __syncthreads();

    // A fragments (fp16)
    u32 aR[4][4][2];
#pragma unroll
    for (int i = 0; i < 4; i++) {
        const int p = 32 * w + 8 * i + g;
#pragma unroll
        for (int kt = 0; kt < 4; kt++)
#pragma unroll
            for (int h = 0; h < 2; h++) {
                const int k0 = 16 * kt + 8 * h + 2 * q;
                aR[i][kt][h] = hf2(sZ[k0 * BLOCK + p], sZ[(k0 + 1) * BLOCK + p]);
            }
    }

    // block max of cn and zn (for certified delta)
    float mx = 0.f, zm = zn;
#pragma unroll
    for (int j = 0; j < K / BLOCK; j++)
        mx = fmaxf(mx, __ldg(&g_cnorm[tid + j * BLOCK]));
#pragma unroll
    for (int o = 16; o > 0; o >>= 1) {
        mx = fmaxf(mx, __shfl_xor_sync(0xffffffffu, mx, o));
        zm = fmaxf(zm, __shfl_xor_sync(0xffffffffu, zm, o));
    }
    if (lane == 0) { sRed[w] = mx; sRed[8 + w] = zm; }
    __syncthreads();
    mx = fmaxf(fmaxf(sRed[0], sRed[1]), fmaxf(sRed[2], sRed[3]));
    zm = fmaxf(fmaxf(sRed[8], sRed[9]), fmaxf(sRed[10], sRed[11]));

    const float delta = 0.030f * sqrtf(zm * mx) + 1e-6f * (zm + mx + 1.0f);
    const u32 dl2 = hf2(delta * 1.05f, delta * 1.05f);
    const u32 INF2 = 0x7C007C00u;
    const u32 M2H2 = 0xC000C000u;
    u32 rm2[4] = {INF2, INF2, INF2, INF2};
    int cnt4[4] = {0, 0, 0, 0};

    const int mSel = lane >> 3;
    const int ntOff = mSel >> 1;
    const int hSel = mSel & 1;
    const int rowIn = lane & 7;

#pragma unroll 1
    for (int grp = 0; grp < NGROUPS; grp++) {
        __syncthreads();
        const uint4* gsrc = (const uint4*)(g_cbpk + (size_t)grp * GROUP * 32);
#pragma unroll
        for (int i = 0; i < 4; i++) {
            int idx = tid + 128 * i;
            u32 off = (u32)idx << 4;
            u32 sw = off ^ ((off >> 3) & 0x70);
            *(uint4*)(smem + OFF_STG + sw) = gsrc[idx];
        }
        __syncthreads();

#pragma unroll 1
        for (int c = 0; c < GROUP / CHUNK; c++) {
            const int cbase = grp * GROUP + c * CHUNK;
            const int lbase = c * CHUNK;

            u32 cfr[2][4][2];
#pragma unroll
            for (int mt = 0; mt < 2; mt++)
#pragma unroll
                for (int nt = 0; nt < 4; nt++) {
                    cfr[mt][nt][0] = 0u;
                    cfr[mt][nt][1] = 0u;
                }
#pragma unroll
            for (int kt = 0; kt < 4; kt++) {
                u32 bb[4][2];
#pragma unroll
                for (int np = 0; np < 2; np++) {
                    const int code = lbase + 8 * (2 * np + ntOff) + rowIn;
                    u32 off = (u32)(code * 128 + kt * 32 + hSel * 16);
                    u32 sw = off ^ ((off >> 3) & 0x70);
                    ldmx4(bb[2 * np][0], bb[2 * np][1],
                          bb[2 * np + 1][0], bb[2 * np + 1][1], sbStg + sw);
                }
#pragma unroll
                for (int mt = 0; mt < 2; mt++)
#pragma unroll
                    for (int nt = 0; nt < 4; nt++)
                        mma16816h(cfr[mt][nt],
                                  aR[2 * mt][kt][0], aR[2 * mt + 1][kt][0],
                                  aR[2 * mt][kt][1], aR[2 * mt + 1][kt][1],
                                  bb[nt][0], bb[nt][1]);
            }

            // fp16x2 screen fast path; inserts carry the f16 score
            u32 cnH[4];
#pragma unroll
            for (int nt = 0; nt < 4; nt++)
                cnH[nt] = sCnH[(cbase >> 1) + 4 * nt + q];
#pragma unroll
            for (int i = 0; i < 4; i++) {
                u32 s0 = hfma2_(cfr[i >> 1][0][i & 1], M2H2, cnH[0]);
                u32 s1 = hfma2_(cfr[i >> 1][1][i & 1], M2H2, cnH[1]);
                u32 s2 = hfma2_(cfr[i >> 1][2][i & 1], M2H2, cnH[2]);
                u32 s3 = hfma2_(cfr[i >> 1][3][i & 1], M2H2, cnH[3]);
                u32 m = hmin2_(hmin2_(s0, s1), hmin2_(s2, s3));
                m = hmin2_(m, hswap_(m));
                rm2[i] = hmin2_(rm2[i], m);
                u32 thr = hadd2_(rm2[i], dl2);
                if (hle2m_(m, thr)) {
                    u32 k0 = hle2m_(s0, thr), k1 = hle2m_(s1, thr);
                    u32 k2 = hle2m_(s2, thr), k3 = hle2m_(s3, thr);
                    const int pidx = 32 * w + 8 * i + g;
                    u32 mk[4] = {k0, k1, k2, k3};
                    u32 sv[4] = {s0, s1, s2, s3};
#pragma unroll
                    for (int nt = 0; nt < 4; nt++) {
                        if (mk[nt] & 0xFFFFu) {
                            if (cnt4[i] < CAPL)
                                sCand[(q * CAPL + cnt4[i]) * BLOCK + pidx] =
                                    (fflip(sv[nt] & 0xFFFFu) << 16) |
                                    (u32)(cbase + 8 * nt + 2 * q);
                            cnt4[i]++;
                        }
                        if (mk[nt] >> 16) {
                            if (cnt4[i] < CAPL)
                                sCand[(q * CAPL + cnt4[i]) * BLOCK + pidx] =
                                    (fflip(sv[nt] >> 16) << 16) |
                                    (u32)(cbase + 8 * nt + 2 * q + 1);
                            cnt4[i]++;
                        }
                    }
                }
            }
#pragma unroll
            for (int i = 0; i < 4; i++) {
                rm2[i] = hmin2_(rm2[i], __shfl_xor_sync(0xffffffffu, rm2[i], 1));
                rm2[i] = hmin2_(rm2[i], __shfl_xor_sync(0xffffffffu, rm2[i], 2));
            }
        }
    }

    // overflow markers (key high half 0xFFFE)
#pragma unroll
    for (int i = 0; i < 4; i++)
        if (cnt4[i] > CAPL) {
            const int pidx = 32 * w + 8 * i + g;
            sCand[(q * CAPL + CAPL - 1) * BLOCK + pidx] = 0xFFFE0000u;
        }
    __syncwarp();

    // refine pass 1: zero-load score min over this point's list (conflict-free)
    u32 minkey = 0xFFFFFFFFu;
    bool ovf = false;
#pragma unroll
    for (int s = 0; s < 64; s++) {
        u32 kk = sCand[s * BLOCK + tid];
        if ((kk >> 16) == 0xFFFEu) { ovf = true; continue; }
        minkey = min(minkey, kk);
    }
    const float minsc = h2f(funflip(minkey >> 16));
    const float thrsc = minsc + delta * 1.05f;

    // refine pass 2: exact eval only certified-near candidates
    float best = 3.4e38f;
    int bestk = 0x7FFFFFFF;
    if (!ovf && minkey != 0xFFFFFFFFu) {
#pragma unroll 1
        for (int s = 0; s < 64; s++) {
            u32 kk = sCand[s * BLOCK + tid];
            if (kk >= 0xFFFE0000u) continue;
            if (h2f(funflip(kk >> 16)) > thrsc) continue;
            const int code = (int)(kk & 0xFFFFu);
            const float4* crow = (const float4*)(cb + (size_t)code * D);
            float dot = 0.f;
#pragma unroll
            for (int qd = 0; qd < 16; qd++) {
                float4 c4 = __ldg(&crow[qd]);
                dot = __fmaf_rn(sZ[(4 * qd + 0) * BLOCK + tid], c4.x, dot);
                dot = __fmaf_rn(sZ[(4 * qd + 1) * BLOCK + tid], c4.y, dot);
                dot = __fmaf_rn(sZ[(4 * qd + 2) * BLOCK + tid], c4.z, dot);
                dot = __fmaf_rn(sZ[(4 * qd + 3) * BLOCK + tid], c4.w, dot);
            }
            float dist = __fsub_rn(__fadd_rn(zn, __ldg(&g_cnorm[code])),
                                   __fmul_rn(2.0f, dot));
            if (dist < best || (dist == best && code < bestk)) {
                best = dist; bestk = code;
            }
        }
    } else {
        // exhaustive exact fallback (never wrong)
        best = 3.4e38f; bestk = 0;
#pragma unroll 1
        for (int code = 0; code < K; code++) {
            const float4* crow = (const float4*)(cb + (size_t)code * D);
            float dot = 0.f;
#pragma unroll
            for (int qd = 0; qd < 16; qd++) {
                float4 c4 = __ldg(&crow[qd]);
                dot = __fmaf_rn(sZ[(4 * qd + 0) * BLOCK + tid], c4.x, dot);
                dot = __fmaf_rn(sZ[(4 * qd + 1) * BLOCK + tid], c4.y, dot);
                dot = __fmaf_rn(sZ[(4 * qd + 2) * BLOCK + tid], c4.z, dot);
                dot = __fmaf_rn(sZ[(4 * qd + 3) * BLOCK + tid], c4.w, dot);
            }
            float dist = __fsub_rn(__fadd_rn(zn, __ldg(&g_cnorm[code])),
                                   __fmul_rn(2.0f, dot));
            if (dist < best) { best = dist; bestk = code; }
        }
    }

    // epilogue (bitwise recipes from R3)
    const float4* qrow = (const float4*)(cb + (size_t)bestk * D);
    float* outz = out + (size_t)b * D * HW + hw;
    float sumsq = 0.f;
#pragma unroll
    for (int i = 0; i < 16; i++) {
        float4 qv = __ldg(&qrow[i]);
        float qq[4] = {qv.x, qv.y, qv.z, qv.w};
#pragma unroll
        for (int j = 0; j < 4; j++) {
            float zv = sZ[(4 * i + j) * BLOCK + tid];
            float dd = __fsub_rn(qq[j], zv);
            float ov = __fadd_rn(zv, dd);
            sumsq += __fmul_rn(dd, dd);
            outz[(size_t)(4 * i + j) * HW] = ov;
        }
    }
    if (idxOff >= 0) out[idxOff + n] = (float)bestk;

#pragma unroll
    for (int o = 16; o > 0; o >>= 1)
        sumsq += __shfl_down_sync(0xffffffffu, sumsq, o);
    __syncthreads();
    if (lane == 0) sRed[w] = sumsq;
    __syncthreads();
    if (tid == 0) {
        float tot = 0.f;
#pragma unroll
        for (int ww = 0; ww < BLOCK / 32; ww++) tot += sRed[ww];
        g_partials[blockIdx.x] = tot;
    }
}

__global__ void loss_kernel(float* __restrict__ out, int nBlocks,
                            long long lossOff, float invN) {
    __shared__ float s[512];
    int tid = threadIdx.x;
    float v = 0.f;
    for (int i = tid; i < nBlocks; i += 512) v += g_partials[i];
    s[tid] = v;
    __syncthreads();
    for (int st = 256; st > 0; st >>= 1) {
        if (tid < st) s[tid] += s[tid + st];
        __syncthreads();
    }
    if (tid == 0 && lossOff >= 0) {
        float m = __fmul_rn(s[0], invN);
        out[lossOff] = __fadd_rn(m, __fmul_rn(0.25f, m));
    }
}

extern "C" void kernel_launch(void* const* d_in, const int* in_sizes, int n_in,
                              void* d_out, int out_size) {
    const float* z = (const float*)d_in[0];
    const float* cb = (const float*)d_in[1];
    float* out = (float*)d_out;

    const int zElems = in_sizes[0];        // 8388608
    const int nPoints = zElems / D;        // 131072
    const int nBlocks = nPoints / BLOCK;   // 1024

    long long lossOff = ((long long)out_size > (long long)zElems) ? (long long)zElems : -1;
    long long idxOff  = ((long long)out_size >= (long long)zElems + 1 + nPoints)
                            ? (long long)zElems + 1 : -1;

    cudaFuncSetAttribute(vq_kernel, cudaFuncAttributeMaxDynamicSharedMemorySize,
                         SMEM_SZ);

    cnorm_pack_kernel<<<K / 64, 64>>>(cb);
    dummy1_kernel<<<1, 32>>>();
    dummy2_kernel<<<1, 32>>>();
    vq_kernel<<<nBlocks, BLOCK, SMEM_SZ>>>(z, cb, out, idxOff);
    loss_kernel<<<1, 512>>>(out, nBlocks, lossOff, 1.0f / (float)zElems);
}